// round 4
// baseline (speedup 1.0000x reference)
#include <cuda_runtime.h>
#include <cuda_bf16.h>
#include <math.h>

// ConstrativeLoss: result = (||sum_i n_i||^2 - sum_i n_i.n_i) / (N * T)
// where n_i = x_i / max(||x_i||, 1e-8). O(N D) single fused kernel,
// software-pipelined loads + 2 CTAs/SM, threadfence last-block reduction.

#define N_ROWS   16384
#define DIMS     512
#define NB       296      // 2 blocks per SM
#define NT       512
#define NW       16
#define TEMP     0.5
#define EPS      1e-8f

// Fixed scratch (allocation-free). Fully overwritten every launch.
__device__ float  g_spart[NB * DIMS];   // 606 KB, L2-resident
__device__ double g_diagpart[NB];
__device__ unsigned int g_count;        // zero-init; last block rearms

__global__ __launch_bounds__(NT, 2) void k_fused(const float* __restrict__ x,
                                                 float* __restrict__ out) {
    __shared__ float4 sh[8 * 128];      // 16 KB staging (tree + final reuse)
    __shared__ double diag_sh[NW];
    __shared__ double shv[128];
    __shared__ double shd[512];
    __shared__ bool   is_last;

    const int w = threadIdx.x >> 5;
    const int l = threadIdx.x & 31;
    const int gwarp = blockIdx.x * NW + w;
    const int nwarps = NB * NW;         // 4736 warps -> 3-4 rows each

    float4 acc[4];
    acc[0] = make_float4(0.f, 0.f, 0.f, 0.f);
    acc[1] = acc[0]; acc[2] = acc[0]; acc[3] = acc[0];
    double diag = 0.0;

    // ---- software-pipelined mainloop: next row's loads issue before the
    //      current row's shuffle/normalize chain ----
    int  row  = gwarp;
    bool have = (row < N_ROWS);
    float4 v[4];
    if (have) {
        const float4* r = reinterpret_cast<const float4*>(x + (size_t)row * DIMS);
#pragma unroll
        for (int p = 0; p < 4; p++) v[p] = r[p * 32 + l];
    }
    while (have) {
        const int  nrow = row + nwarps;
        const bool hn   = (nrow < N_ROWS);
        float4 vn[4];
        if (hn) {
            const float4* r = reinterpret_cast<const float4*>(x + (size_t)nrow * DIMS);
#pragma unroll
            for (int p = 0; p < 4; p++) vn[p] = r[p * 32 + l];   // in flight now
        }

        float ss = 0.f;
#pragma unroll
        for (int p = 0; p < 4; p++)
            ss += v[p].x * v[p].x + v[p].y * v[p].y
                + v[p].z * v[p].z + v[p].w * v[p].w;
#pragma unroll
        for (int o = 16; o > 0; o >>= 1)
            ss += __shfl_xor_sync(0xFFFFFFFFu, ss, o);

        float inv = 1.0f / fmaxf(sqrtf(ss), EPS);
        if (l == 0) diag += (double)(ss * inv * inv);
#pragma unroll
        for (int p = 0; p < 4; p++) {
            acc[p].x += v[p].x * inv;
            acc[p].y += v[p].y * inv;
            acc[p].z += v[p].z * inv;
            acc[p].w += v[p].w * inv;
        }

#pragma unroll
        for (int p = 0; p < 4; p++) v[p] = vn[p];
        row = nrow; have = hn;
    }

    // ---- block combine: halving tree over 16 warps (fixed order) ----
#pragma unroll
    for (int half = 8; half >= 1; half >>= 1) {
        if (w >= half && w < 2 * half) {
            int dst = (w - half) * 128;
#pragma unroll
            for (int p = 0; p < 4; p++)
                sh[dst + p * 32 + l] = acc[p];
        }
        __syncthreads();
        if (w < half) {
#pragma unroll
            for (int p = 0; p < 4; p++) {
                float4 a = sh[w * 128 + p * 32 + l];
                acc[p].x += a.x; acc[p].y += a.y;
                acc[p].z += a.z; acc[p].w += a.w;
            }
        }
        __syncthreads();
    }
    if (l == 0) diag_sh[w] = diag;
    __syncthreads();

    if (w == 0) {
        float4* gp = reinterpret_cast<float4*>(g_spart + (size_t)blockIdx.x * DIMS);
#pragma unroll
        for (int p = 0; p < 4; p++)
            gp[p * 32 + l] = acc[p];
        if (l == 0) {
            double d = 0.0;
#pragma unroll
            for (int ww = 0; ww < NW; ww++) d += diag_sh[ww];
            g_diagpart[blockIdx.x] = d;
        }
    }

    // ---- last-block final reduction (deterministic: fixed-order sums) ----
    __threadfence();
    if (threadIdx.x == 0) {
        unsigned int old = atomicAdd(&g_count, 1u);
        is_last = (old == NB - 1);
    }
    __syncthreads();

    if (is_last) {
        __threadfence();
        const int t = threadIdx.x;
        const int c4 = t & 127;          // float4 column 0..127
        const int slice = t >> 7;        // 0..3 over blocks; 296/4 = 74 each
        const float4* sp = reinterpret_cast<const float4*>(g_spart);

        float4 pa[4];
        pa[0] = make_float4(0.f, 0.f, 0.f, 0.f);
        pa[1] = pa[0]; pa[2] = pa[0]; pa[3] = pa[0];
#pragma unroll 4
        for (int i = 0; i < 74; i++) {   // 74 independent L2-hot LDG.128
            int b = slice + 4 * i;
            float4 a = sp[(size_t)b * 128 + c4];
            pa[i & 3].x += a.x; pa[i & 3].y += a.y;
            pa[i & 3].z += a.z; pa[i & 3].w += a.w;
        }
        float4 ps;
        ps.x = (pa[0].x + pa[1].x) + (pa[2].x + pa[3].x);
        ps.y = (pa[0].y + pa[1].y) + (pa[2].y + pa[3].y);
        ps.z = (pa[0].z + pa[1].z) + (pa[2].z + pa[3].z);
        ps.w = (pa[0].w + pa[1].w) + (pa[2].w + pa[3].w);

        sh[t] = ps;
        __syncthreads();

        if (t < 128) {                   // combine 4 slices in fixed order
            float4 s = sh[t];
#pragma unroll
            for (int q = 1; q < 4; q++) {
                float4 a = sh[q * 128 + t];
                s.x += a.x; s.y += a.y; s.z += a.z; s.w += a.w;
            }
            shv[t] = (double)s.x * (double)s.x + (double)s.y * (double)s.y
                   + (double)s.z * (double)s.z + (double)s.w * (double)s.w;
        }
        shd[t] = (t < NB) ? g_diagpart[t] : 0.0;
        __syncthreads();

#pragma unroll
        for (int o = 256; o > 0; o >>= 1) {
            if (t < o) shd[t] += shd[t + o];
            if (o <= 64 && t < o) shv[t] += shv[t + o];
            __syncthreads();
        }
        if (t == 0) {
            double num = shv[0] - shd[0];
            out[0] = (float)(num / ((double)N_ROWS * TEMP));
            g_count = 0;                 // rearm for next graph replay
        }
    }
}

extern "C" void kernel_launch(void* const* d_in, const int* in_sizes, int n_in,
                              void* d_out, int out_size) {
    const float* x = (const float*)d_in[0];
    float* out = (float*)d_out;
    k_fused<<<NB, NT>>>(x, out);
}

// round 5
// speedup vs baseline: 1.2429x; 1.2429x over previous
#include <cuda_runtime.h>
#include <cuda_bf16.h>
#include <math.h>

// ConstrativeLoss: result = (||sum_i n_i||^2 - sum_i n_i.n_i) / (N * T)
// with n_i = x_i / max(||x_i||, 1e-8). O(N D). Single launch:
//   phase 1: R2's proven streaming config (512 x 256), per-block partials
//   phase 2: 32 blocks spin-barrier, each sums 16 partial rows
//   phase 3: last phase-2 block reduces 32 rows + diag -> scalar
// Determinism: int-only atomics, all float/double sums in fixed order.

#define N_ROWS   16384
#define DIMS     512
#define NB       512
#define NT       256
#define NW       8
#define NB2      32       // phase-2 blocks
#define ROWS_PER 16       // partial rows per phase-2 block
#define TEMP     0.5
#define EPS      1e-8f

__device__ float  g_spart[NB * DIMS];     // 1 MB partials (L2-resident)
__device__ float  g_stage2[NB2 * DIMS];   // 64 KB stage-2 partials
__device__ double g_diagpart[NB];
__device__ unsigned int g_count1;         // phase1 done counter (rearmed)
__device__ unsigned int g_count2;         // phase2 done counter (rearmed)

__global__ __launch_bounds__(NT) void k_fused(const float* __restrict__ x,
                                              float* __restrict__ out) {
    __shared__ float4 s_sh4[NW * (DIMS / 4)];   // 16 KB
    __shared__ double diag_sh[NW];
    __shared__ double shv[128];
    __shared__ double shd[256];
    __shared__ bool   is_last;

    const int w = threadIdx.x >> 5;
    const int l = threadIdx.x & 31;
    const int gwarp = blockIdx.x * NW + w;
    const int nwarps = NB * NW;                 // 4096 warps -> 4 rows each

    // ================= phase 1: streaming (identical to R2 k_rows) ========
    float4 acc[4];
    acc[0] = make_float4(0.f, 0.f, 0.f, 0.f);
    acc[1] = acc[0]; acc[2] = acc[0]; acc[3] = acc[0];
    double diag = 0.0;

    for (int row = gwarp; row < N_ROWS; row += nwarps) {
        const float4* xr = reinterpret_cast<const float4*>(x + (size_t)row * DIMS);
        float4 v[4];
        float ss = 0.f;
#pragma unroll
        for (int p = 0; p < 4; p++) {
            v[p] = xr[p * 32 + l];
            ss += v[p].x * v[p].x + v[p].y * v[p].y
                + v[p].z * v[p].z + v[p].w * v[p].w;
        }
#pragma unroll
        for (int o = 16; o > 0; o >>= 1)
            ss += __shfl_xor_sync(0xFFFFFFFFu, ss, o);

        float nrm = fmaxf(sqrtf(ss), EPS);
        float inv = 1.0f / nrm;
        if (l == 0)
            diag += (double)(ss * inv * inv);

#pragma unroll
        for (int p = 0; p < 4; p++) {
            acc[p].x += v[p].x * inv;
            acc[p].y += v[p].y * inv;
            acc[p].z += v[p].z * inv;
            acc[p].w += v[p].w * inv;
        }
    }

    // stash per-warp partials (ordered combine, deterministic)
#pragma unroll
    for (int p = 0; p < 4; p++)
        s_sh4[w * 128 + p * 32 + l] = acc[p];
    if (l == 0)
        diag_sh[w] = diag;
    __syncthreads();

    const int t = threadIdx.x;
    if (t < 128) {
        float4 sum = s_sh4[t];
#pragma unroll
        for (int ww = 1; ww < NW; ww++) {
            float4 a = s_sh4[ww * 128 + t];
            sum.x += a.x; sum.y += a.y; sum.z += a.z; sum.w += a.w;
        }
        reinterpret_cast<float4*>(g_spart + (size_t)blockIdx.x * DIMS)[t] = sum;
    }
    if (t == 0) {
        double d = 0.0;
#pragma unroll
        for (int ww = 0; ww < NW; ww++) d += diag_sh[ww];
        g_diagpart[blockIdx.x] = d;
    }

    __threadfence();
    if (t == 0) atomicAdd(&g_count1, 1u);

    // ================= phase 2: 32 blocks, 16 rows each ===================
    if (blockIdx.x >= NB2) return;

    if (t == 0) {
        while (atomicAdd(&g_count1, 0u) < NB) { /* spin, single wave */ }
    }
    __syncthreads();
    __threadfence();

    if (t < 128) {
        const float4* sp = reinterpret_cast<const float4*>(g_spart);
        const int base = blockIdx.x * ROWS_PER;
        float4 pa[4];
        pa[0] = make_float4(0.f, 0.f, 0.f, 0.f);
        pa[1] = pa[0]; pa[2] = pa[0]; pa[3] = pa[0];
#pragma unroll
        for (int i = 0; i < ROWS_PER; i++) {    // 16 independent LDG.128
            float4 a = sp[(size_t)(base + i) * 128 + t];
            pa[i & 3].x += a.x; pa[i & 3].y += a.y;
            pa[i & 3].z += a.z; pa[i & 3].w += a.w;
        }
        float4 ps;
        ps.x = (pa[0].x + pa[1].x) + (pa[2].x + pa[3].x);
        ps.y = (pa[0].y + pa[1].y) + (pa[2].y + pa[3].y);
        ps.z = (pa[0].z + pa[1].z) + (pa[2].z + pa[3].z);
        ps.w = (pa[0].w + pa[1].w) + (pa[2].w + pa[3].w);
        reinterpret_cast<float4*>(g_stage2 + (size_t)blockIdx.x * DIMS)[t] = ps;
    }

    __threadfence();
    __syncthreads();
    if (t == 0) {
        unsigned int old = atomicAdd(&g_count2, 1u);
        is_last = (old == NB2 - 1);
    }
    __syncthreads();
    if (!is_last) return;

    // ================= phase 3: final scalar ==============================
    __threadfence();
    {
        const int c4 = t & 127;          // float4 column 0..127
        const int half = t >> 7;         // 0..1 over stage-2 rows (16 each)
        const float4* sp = reinterpret_cast<const float4*>(g_stage2);

        float4 pa[4];
        pa[0] = make_float4(0.f, 0.f, 0.f, 0.f);
        pa[1] = pa[0]; pa[2] = pa[0]; pa[3] = pa[0];
#pragma unroll
        for (int i = 0; i < 16; i++) {
            int r = half * 16 + i;
            float4 a = sp[(size_t)r * 128 + c4];
            pa[i & 3].x += a.x; pa[i & 3].y += a.y;
            pa[i & 3].z += a.z; pa[i & 3].w += a.w;
        }
        float4 ps;
        ps.x = (pa[0].x + pa[1].x) + (pa[2].x + pa[3].x);
        ps.y = (pa[0].y + pa[1].y) + (pa[2].y + pa[3].y);
        ps.z = (pa[0].z + pa[1].z) + (pa[2].z + pa[3].z);
        ps.w = (pa[0].w + pa[1].w) + (pa[2].w + pa[3].w);

        s_sh4[t] = ps;                   // reuse 16 KB staging
        __syncthreads();

        if (t < 128) {                   // combine the 2 halves, fixed order
            float4 a = s_sh4[t];
            float4 b = s_sh4[128 + t];
            double sx = (double)(a.x + b.x), sy = (double)(a.y + b.y);
            double sz = (double)(a.z + b.z), sw = (double)(a.w + b.w);
            shv[t] = sx * sx + sy * sy + sz * sz + sw * sw;
        }
        // diag: 512 doubles, 2 per thread, fixed order
        shd[t] = g_diagpart[t] + g_diagpart[t + 256];
        __syncthreads();

#pragma unroll
        for (int o = 128; o > 0; o >>= 1) {
            if (t < o) shd[t] += shd[t + o];
            if (o <= 64 && t < o) shv[t] += shv[t + o];
            __syncthreads();
        }
        if (t == 0) {
            double num = shv[0] - shd[0];
            out[0] = (float)(num / ((double)N_ROWS * TEMP));
            g_count1 = 0;                // rearm for next graph replay
            g_count2 = 0;
        }
    }
}

extern "C" void kernel_launch(void* const* d_in, const int* in_sizes, int n_in,
                              void* d_out, int out_size) {
    const float* x = (const float*)d_in[0];
    float* out = (float*)d_out;
    k_fused<<<NB, NT>>>(x, out);
}